// round 1
// baseline (speedup 1.0000x reference)
#include <cuda_runtime.h>

#define D_MODEL 1024
#define LSEQ    2048
#define NB      2
#define NHEAD   16
#define HD      64
#define NTOK    (NB * LSEQ)   // 4096

// Scratch (device globals — alloc-free per harness rules)
__device__ float g_qkv[(size_t)NTOK * 3 * D_MODEL];   // [4096, 3072]
__device__ float g_attn[(size_t)NTOK * D_MODEL];      // [4096, 1024] = [B,L,H,hd]

// ---------------------------------------------------------------------------
// GEMM: C[M,N] = A[M,K] @ B[K,N] + bias[N]
// 64x64 tile, BK=16, 256 threads, 4x4 per thread.
// ---------------------------------------------------------------------------
__global__ void gemm_bias_kernel(const float* __restrict__ A,
                                 const float* __restrict__ B,
                                 const float* __restrict__ bias,
                                 float* __restrict__ C,
                                 int M, int N, int K) {
    __shared__ float As[16][65];   // [k][m], padded: conflict-free writes & broadcast reads
    __shared__ float Bs[16][68];   // [k][n], padded; rows stay 16B aligned (68*4=272)

    const int tx = threadIdx.x;            // 0..15
    const int ty = threadIdx.y;            // 0..15
    const int tid = ty * 16 + tx;
    const int rowBase = blockIdx.y * 64;
    const int colBase = blockIdx.x * 64;

    float acc[4][4] = {};

    for (int k0 = 0; k0 < K; k0 += 16) {
        // Load A tile 64x16 (row-major global, store transposed into As[k][m])
        #pragma unroll
        for (int i = tid; i < 64 * 16; i += 256) {
            int m = i >> 4, k = i & 15;
            As[k][m] = A[(size_t)(rowBase + m) * K + k0 + k];
        }
        // Load B tile 16x64 (coalesced)
        #pragma unroll
        for (int i = tid; i < 16 * 64; i += 256) {
            int k = i >> 6, n = i & 63;
            Bs[k][n] = B[(size_t)(k0 + k) * N + colBase + n];
        }
        __syncthreads();

        #pragma unroll
        for (int k = 0; k < 16; k++) {
            float a[4];
            #pragma unroll
            for (int i = 0; i < 4; i++) a[i] = As[k][ty * 4 + i];
            float4 bv = *reinterpret_cast<const float4*>(&Bs[k][tx * 4]);
            float b[4] = {bv.x, bv.y, bv.z, bv.w};
            #pragma unroll
            for (int i = 0; i < 4; i++)
                #pragma unroll
                for (int j = 0; j < 4; j++)
                    acc[i][j] += a[i] * b[j];
        }
        __syncthreads();
    }

    #pragma unroll
    for (int i = 0; i < 4; i++) {
        int r = rowBase + ty * 4 + i;
        #pragma unroll
        for (int j = 0; j < 4; j++) {
            int c = colBase + tx * 4 + j;
            C[(size_t)r * N + c] = acc[i][j] + bias[c];
        }
    }
}

// ---------------------------------------------------------------------------
// Causal attention, flash-style online softmax.
// Block = (16,16) threads handles one (b, h, 64-row Q tile).
// KV tiles of 32 rows. hd = 64.
// ---------------------------------------------------------------------------
__global__ void attn_kernel() {
    const int qt = blockIdx.x;   // 0..31
    const int h  = blockIdx.y;   // 0..15
    const int b  = blockIdx.z;   // 0..1

    __shared__ float Qs[64][65];
    __shared__ float Ks[32][65];
    __shared__ float Vs[32][65];
    __shared__ float Ps[64][36];

    const int tx = threadIdx.x, ty = threadIdx.y;
    const int tid = ty * 16 + tx;
    const float scale = 0.125f;  // 1/sqrt(64)
    const int qrow0 = qt * 64;

    // Load Q tile [64, 64]
    for (int i = tid; i < 64 * 64; i += 256) {
        int r = i >> 6, d = i & 63;
        Qs[r][d] = g_qkv[(size_t)(b * LSEQ + qrow0 + r) * 3072 + h * 64 + d];
    }

    float m_i[4], l_i[4], acc[4][4];
    #pragma unroll
    for (int i = 0; i < 4; i++) {
        m_i[i] = -1e30f; l_i[i] = 0.0f;
        #pragma unroll
        for (int j = 0; j < 4; j++) acc[i][j] = 0.0f;
    }
    __syncthreads();

    const int nkt = 2 * qt + 2;  // 32-row KV tiles covering [0, qrow0+64)
    for (int kt = 0; kt < nkt; kt++) {
        const int kv0 = kt * 32;
        // Load K,V tiles [32, 64]
        for (int i = tid; i < 32 * 64; i += 256) {
            int r = i >> 6, d = i & 63;
            size_t row = (size_t)(b * LSEQ + kv0 + r) * 3072 + h * 64 + d;
            Ks[r][d] = g_qkv[row + 1024];
            Vs[r][d] = g_qkv[row + 2048];
        }
        __syncthreads();

        // S = scale * Q @ K^T : rows ty*4+i (4), cols tx*2+j (2)
        float s[4][2] = {};
        #pragma unroll 8
        for (int k = 0; k < 64; k++) {
            float a0 = Qs[ty * 4 + 0][k];
            float a1 = Qs[ty * 4 + 1][k];
            float a2 = Qs[ty * 4 + 2][k];
            float a3 = Qs[ty * 4 + 3][k];
            float c0 = Ks[tx * 2 + 0][k];
            float c1 = Ks[tx * 2 + 1][k];
            s[0][0] += a0 * c0; s[0][1] += a0 * c1;
            s[1][0] += a1 * c0; s[1][1] += a1 * c1;
            s[2][0] += a2 * c0; s[2][1] += a2 * c1;
            s[3][0] += a3 * c0; s[3][1] += a3 * c1;
        }
        #pragma unroll
        for (int i = 0; i < 4; i++)
            #pragma unroll
            for (int j = 0; j < 2; j++) s[i][j] *= scale;

        // Causal mask (only the last two tiles can cross the diagonal)
        if (kt >= 2 * qt) {
            #pragma unroll
            for (int i = 0; i < 4; i++) {
                int qr = qrow0 + ty * 4 + i;
                #pragma unroll
                for (int j = 0; j < 2; j++) {
                    int kc = kv0 + tx * 2 + j;
                    if (kc > qr) s[i][j] = -1e30f;
                }
            }
        }

        // Online softmax, row stats reduced across the 16 tx lanes
        #pragma unroll
        for (int i = 0; i < 4; i++) {
            float mt = fmaxf(s[i][0], s[i][1]);
            #pragma unroll
            for (int off = 1; off < 16; off <<= 1)
                mt = fmaxf(mt, __shfl_xor_sync(0xffffffffu, mt, off));
            float mnew = fmaxf(m_i[i], mt);
            float p0 = __expf(s[i][0] - mnew);
            float p1 = __expf(s[i][1] - mnew);
            float rs = p0 + p1;
            #pragma unroll
            for (int off = 1; off < 16; off <<= 1)
                rs += __shfl_xor_sync(0xffffffffu, rs, off);
            float alpha = __expf(m_i[i] - mnew);
            l_i[i] = l_i[i] * alpha + rs;
            m_i[i] = mnew;
            #pragma unroll
            for (int j = 0; j < 4; j++) acc[i][j] *= alpha;
            Ps[ty * 4 + i][tx * 2 + 0] = p0;
            Ps[ty * 4 + i][tx * 2 + 1] = p1;
        }
        __syncthreads();

        // acc += P[64,32] @ V[32,64] : this thread owns hd cols tx*4+j
        #pragma unroll 8
        for (int k = 0; k < 32; k++) {
            float p0 = Ps[ty * 4 + 0][k];
            float p1 = Ps[ty * 4 + 1][k];
            float p2 = Ps[ty * 4 + 2][k];
            float p3 = Ps[ty * 4 + 3][k];
            #pragma unroll
            for (int j = 0; j < 4; j++) {
                float v = Vs[k][tx * 4 + j];
                acc[0][j] += p0 * v;
                acc[1][j] += p1 * v;
                acc[2][j] += p2 * v;
                acc[3][j] += p3 * v;
            }
        }
        __syncthreads();
    }

    // Epilogue: normalize and store to [B, L, H, hd] layout
    #pragma unroll
    for (int i = 0; i < 4; i++) {
        float inv = 1.0f / l_i[i];
        size_t row = (size_t)(b * LSEQ + qrow0 + ty * 4 + i) * D_MODEL + h * 64;
        #pragma unroll
        for (int j = 0; j < 4; j++)
            g_attn[row + tx * 4 + j] = acc[i][j] * inv;
    }
}

// ---------------------------------------------------------------------------
extern "C" void kernel_launch(void* const* d_in, const int* in_sizes, int n_in,
                              void* d_out, int out_size) {
    const float* x     = (const float*)d_in[0];  // [2, 2048, 1024]
    const float* W_qkv = (const float*)d_in[1];  // [1024, 3072]
    const float* b_qkv = (const float*)d_in[2];  // [3072]
    const float* W_out = (const float*)d_in[3];  // [1024, 1024]
    const float* b_out = (const float*)d_in[4];  // [1024]
    float* out = (float*)d_out;                  // [2, 2048, 1024]

    float* qkv;  cudaGetSymbolAddress((void**)&qkv,  g_qkv);
    float* attn; cudaGetSymbolAddress((void**)&attn, g_attn);

    dim3 blk(16, 16);

    // 1) QKV projection: [4096,1024] @ [1024,3072] + b
    dim3 g1(3 * D_MODEL / 64, NTOK / 64);
    gemm_bias_kernel<<<g1, blk>>>(x, W_qkv, b_qkv, qkv, NTOK, 3 * D_MODEL, D_MODEL);

    // 2) Causal attention
    dim3 g2(LSEQ / 64, NHEAD, NB);
    attn_kernel<<<g2, blk>>>();

    // 3) Output projection: [4096,1024] @ [1024,1024] + b
    dim3 g3(D_MODEL / 64, NTOK / 64);
    gemm_bias_kernel<<<g3, blk>>>(attn, W_out, b_out, out, NTOK, D_MODEL, D_MODEL);
}

// round 2
// speedup vs baseline: 1.6481x; 1.6481x over previous
#include <cuda_runtime.h>
#include <cstdint>

#define D_MODEL 1024
#define LSEQ    2048
#define NB      2
#define NHEAD   16
#define HD      64
#define NTOK    (NB * LSEQ)   // 4096

// Scratch (device globals — alloc-free per harness rules)
__device__ float g_qkv[(size_t)NTOK * 3 * D_MODEL];   // [4096, 3072]
__device__ float g_attn[(size_t)NTOK * D_MODEL];      // [4096, 1024] = [B,L,H,hd]

// ---------------------------------------------------------------------------
// tf32 helpers
// ---------------------------------------------------------------------------
__device__ __forceinline__ uint32_t f2tf32(float f) {
    uint32_t r;
    asm("cvt.rna.tf32.f32 %0, %1;" : "=r"(r) : "f"(f));
    return r;
}

__device__ __forceinline__ void mma_tf32(float c[4], const uint32_t a[4], const uint32_t b[2]) {
    asm volatile(
        "mma.sync.aligned.m16n8k8.row.col.f32.tf32.tf32.f32 "
        "{%0,%1,%2,%3}, {%4,%5,%6,%7}, {%8,%9}, {%0,%1,%2,%3};"
        : "+f"(c[0]), "+f"(c[1]), "+f"(c[2]), "+f"(c[3])
        : "r"(a[0]), "r"(a[1]), "r"(a[2]), "r"(a[3]),
          "r"(b[0]), "r"(b[1]));
}

// ---------------------------------------------------------------------------
// tf32 tensor-core GEMM: C[M,N] = A[M,K] @ B[K,N] + bias[N]
// Block tile 128x128, BK=16, 256 threads = 8 warps (2 M x 4 N),
// warp tile 64x32 = 4x4 m16n8k8 mma tiles.
// smem [k][m]/[k][n] with pad=4 -> conflict-free fragment LDS.
// ---------------------------------------------------------------------------
__global__ __launch_bounds__(256, 2)
void gemm_tf32_kernel(const float* __restrict__ A,
                      const float* __restrict__ B,
                      const float* __restrict__ bias,
                      float* __restrict__ C,
                      int M, int N, int K) {
    __shared__ uint32_t As[16][132];   // [k][m], tf32 bits
    __shared__ uint32_t Bs[16][132];   // [k][n], tf32 bits

    const int tid  = threadIdx.x;
    const int w    = tid >> 5;
    const int lane = tid & 31;
    const int gid  = lane >> 2;   // 0..7
    const int tig  = lane & 3;    // 0..3
    const int wm   = w >> 2;      // 0..1 : M offset wm*64
    const int wn   = w & 3;       // 0..3 : N offset wn*32

    const int rowBase = blockIdx.y * 128;
    const int colBase = blockIdx.x * 128;

    float acc[4][4][4];
    #pragma unroll
    for (int mt = 0; mt < 4; mt++)
        #pragma unroll
        for (int nt = 0; nt < 4; nt++)
            #pragma unroll
            for (int r = 0; r < 4; r++) acc[mt][nt][r] = 0.0f;

    for (int k0 = 0; k0 < K; k0 += 16) {
        // Load A tile 128x16 (transpose into As[k][m]), convert to tf32
        #pragma unroll
        for (int i = tid; i < 512; i += 256) {
            int m  = i >> 2;            // 0..127
            int kq = (i & 3) << 2;      // 0,4,8,12
            float4 v = *reinterpret_cast<const float4*>(
                &A[(size_t)(rowBase + m) * K + k0 + kq]);
            As[kq + 0][m] = f2tf32(v.x);
            As[kq + 1][m] = f2tf32(v.y);
            As[kq + 2][m] = f2tf32(v.z);
            As[kq + 3][m] = f2tf32(v.w);
        }
        // Load B tile 16x128 (coalesced), convert to tf32
        #pragma unroll
        for (int i = tid; i < 512; i += 256) {
            int k  = i >> 5;            // 0..15
            int nq = (i & 31) << 2;     // 0..124
            float4 v = *reinterpret_cast<const float4*>(
                &B[(size_t)(k0 + k) * N + colBase + nq]);
            Bs[k][nq + 0] = f2tf32(v.x);
            Bs[k][nq + 1] = f2tf32(v.y);
            Bs[k][nq + 2] = f2tf32(v.z);
            Bs[k][nq + 3] = f2tf32(v.w);
        }
        __syncthreads();

        #pragma unroll
        for (int kk = 0; kk < 2; kk++) {
            const int kb = kk * 8;
            uint32_t afr[4][4], bfr[4][2];
            #pragma unroll
            for (int mt = 0; mt < 4; mt++) {
                int m = wm * 64 + mt * 16;
                afr[mt][0] = As[kb + tig    ][m + gid    ];
                afr[mt][1] = As[kb + tig    ][m + gid + 8];
                afr[mt][2] = As[kb + tig + 4][m + gid    ];
                afr[mt][3] = As[kb + tig + 4][m + gid + 8];
            }
            #pragma unroll
            for (int nt = 0; nt < 4; nt++) {
                int n = wn * 32 + nt * 8;
                bfr[nt][0] = Bs[kb + tig    ][n + gid];
                bfr[nt][1] = Bs[kb + tig + 4][n + gid];
            }
            #pragma unroll
            for (int mt = 0; mt < 4; mt++)
                #pragma unroll
                for (int nt = 0; nt < 4; nt++)
                    mma_tf32(acc[mt][nt], afr[mt], bfr[nt]);
        }
        __syncthreads();
    }

    // Epilogue: add bias, store as float2 pairs
    #pragma unroll
    for (int mt = 0; mt < 4; mt++) {
        int r0 = rowBase + wm * 64 + mt * 16 + gid;
        #pragma unroll
        for (int nt = 0; nt < 4; nt++) {
            int c0 = colBase + wn * 32 + nt * 8 + 2 * tig;
            float bi0 = bias[c0], bi1 = bias[c0 + 1];
            float2 v0 = make_float2(acc[mt][nt][0] + bi0, acc[mt][nt][1] + bi1);
            float2 v1 = make_float2(acc[mt][nt][2] + bi0, acc[mt][nt][3] + bi1);
            *reinterpret_cast<float2*>(&C[(size_t)r0       * N + c0]) = v0;
            *reinterpret_cast<float2*>(&C[(size_t)(r0 + 8) * N + c0]) = v1;
        }
    }
}

// ---------------------------------------------------------------------------
// Causal attention, flash-style online softmax (fp32 SIMT, unchanged R0).
// Block = (16,16) threads handles one (b, h, 64-row Q tile).
// ---------------------------------------------------------------------------
__global__ void attn_kernel() {
    const int qt = blockIdx.x;   // 0..31
    const int h  = blockIdx.y;   // 0..15
    const int b  = blockIdx.z;   // 0..1

    __shared__ float Qs[64][65];
    __shared__ float Ks[32][65];
    __shared__ float Vs[32][65];
    __shared__ float Ps[64][36];

    const int tx = threadIdx.x, ty = threadIdx.y;
    const int tid = ty * 16 + tx;
    const float scale = 0.125f;  // 1/sqrt(64)
    const int qrow0 = qt * 64;

    for (int i = tid; i < 64 * 64; i += 256) {
        int r = i >> 6, d = i & 63;
        Qs[r][d] = g_qkv[(size_t)(b * LSEQ + qrow0 + r) * 3072 + h * 64 + d];
    }

    float m_i[4], l_i[4], acc[4][4];
    #pragma unroll
    for (int i = 0; i < 4; i++) {
        m_i[i] = -1e30f; l_i[i] = 0.0f;
        #pragma unroll
        for (int j = 0; j < 4; j++) acc[i][j] = 0.0f;
    }
    __syncthreads();

    const int nkt = 2 * qt + 2;
    for (int kt = 0; kt < nkt; kt++) {
        const int kv0 = kt * 32;
        for (int i = tid; i < 32 * 64; i += 256) {
            int r = i >> 6, d = i & 63;
            size_t row = (size_t)(b * LSEQ + kv0 + r) * 3072 + h * 64 + d;
            Ks[r][d] = g_qkv[row + 1024];
            Vs[r][d] = g_qkv[row + 2048];
        }
        __syncthreads();

        float s[4][2] = {};
        #pragma unroll 8
        for (int k = 0; k < 64; k++) {
            float a0 = Qs[ty * 4 + 0][k];
            float a1 = Qs[ty * 4 + 1][k];
            float a2 = Qs[ty * 4 + 2][k];
            float a3 = Qs[ty * 4 + 3][k];
            float c0 = Ks[tx * 2 + 0][k];
            float c1 = Ks[tx * 2 + 1][k];
            s[0][0] += a0 * c0; s[0][1] += a0 * c1;
            s[1][0] += a1 * c0; s[1][1] += a1 * c1;
            s[2][0] += a2 * c0; s[2][1] += a2 * c1;
            s[3][0] += a3 * c0; s[3][1] += a3 * c1;
        }
        #pragma unroll
        for (int i = 0; i < 4; i++)
            #pragma unroll
            for (int j = 0; j < 2; j++) s[i][j] *= scale;

        if (kt >= 2 * qt) {
            #pragma unroll
            for (int i = 0; i < 4; i++) {
                int qr = qrow0 + ty * 4 + i;
                #pragma unroll
                for (int j = 0; j < 2; j++) {
                    int kc = kv0 + tx * 2 + j;
                    if (kc > qr) s[i][j] = -1e30f;
                }
            }
        }

        #pragma unroll
        for (int i = 0; i < 4; i++) {
            float mt = fmaxf(s[i][0], s[i][1]);
            #pragma unroll
            for (int off = 1; off < 16; off <<= 1)
                mt = fmaxf(mt, __shfl_xor_sync(0xffffffffu, mt, off));
            float mnew = fmaxf(m_i[i], mt);
            float p0 = __expf(s[i][0] - mnew);
            float p1 = __expf(s[i][1] - mnew);
            float rs = p0 + p1;
            #pragma unroll
            for (int off = 1; off < 16; off <<= 1)
                rs += __shfl_xor_sync(0xffffffffu, rs, off);
            float alpha = __expf(m_i[i] - mnew);
            l_i[i] = l_i[i] * alpha + rs;
            m_i[i] = mnew;
            #pragma unroll
            for (int j = 0; j < 4; j++) acc[i][j] *= alpha;
            Ps[ty * 4 + i][tx * 2 + 0] = p0;
            Ps[ty * 4 + i][tx * 2 + 1] = p1;
        }
        __syncthreads();

        #pragma unroll 8
        for (int k = 0; k < 32; k++) {
            float p0 = Ps[ty * 4 + 0][k];
            float p1 = Ps[ty * 4 + 1][k];
            float p2 = Ps[ty * 4 + 2][k];
            float p3 = Ps[ty * 4 + 3][k];
            #pragma unroll
            for (int j = 0; j < 4; j++) {
                float v = Vs[k][tx * 4 + j];
                acc[0][j] += p0 * v;
                acc[1][j] += p1 * v;
                acc[2][j] += p2 * v;
                acc[3][j] += p3 * v;
            }
        }
        __syncthreads();
    }

    #pragma unroll
    for (int i = 0; i < 4; i++) {
        float inv = 1.0f / l_i[i];
        size_t row = (size_t)(b * LSEQ + qrow0 + ty * 4 + i) * D_MODEL + h * 64;
        #pragma unroll
        for (int j = 0; j < 4; j++)
            g_attn[row + tx * 4 + j] = acc[i][j] * inv;
    }
}

// ---------------------------------------------------------------------------
extern "C" void kernel_launch(void* const* d_in, const int* in_sizes, int n_in,
                              void* d_out, int out_size) {
    const float* x     = (const float*)d_in[0];  // [2, 2048, 1024]
    const float* W_qkv = (const float*)d_in[1];  // [1024, 3072]
    const float* b_qkv = (const float*)d_in[2];  // [3072]
    const float* W_out = (const float*)d_in[3];  // [1024, 1024]
    const float* b_out = (const float*)d_in[4];  // [1024]
    float* out = (float*)d_out;                  // [2, 2048, 1024]

    float* qkv;  cudaGetSymbolAddress((void**)&qkv,  g_qkv);
    float* attn; cudaGetSymbolAddress((void**)&attn, g_attn);

    // 1) QKV projection: [4096,1024] @ [1024,3072] + b   (tf32 tensor cores)
    dim3 g1(3 * D_MODEL / 128, NTOK / 128);
    gemm_tf32_kernel<<<g1, 256>>>(x, W_qkv, b_qkv, qkv, NTOK, 3 * D_MODEL, D_MODEL);

    // 2) Causal attention (fp32 SIMT)
    dim3 g2(LSEQ / 64, NHEAD, NB);
    attn_kernel<<<g2, dim3(16, 16)>>>();

    // 3) Output projection: [4096,1024] @ [1024,1024] + b (tf32 tensor cores)
    dim3 g3(D_MODEL / 128, NTOK / 128);
    gemm_tf32_kernel<<<g3, 256>>>(attn, W_out, b_out, out, NTOK, D_MODEL, D_MODEL);
}

// round 3
// speedup vs baseline: 3.1465x; 1.9091x over previous
#include <cuda_runtime.h>
#include <cstdint>

#define D_MODEL 1024
#define LSEQ    2048
#define NB      2
#define NHEAD   16
#define HD      64
#define NTOK    (NB * LSEQ)   // 4096

// Scratch (device globals — alloc-free per harness rules)
__device__ float g_qkv[(size_t)NTOK * 3 * D_MODEL];   // [4096, 3072]
__device__ float g_attn[(size_t)NTOK * D_MODEL];      // [4096, 1024] = [B,L,H,hd]

// ---------------------------------------------------------------------------
// tf32 helpers
// ---------------------------------------------------------------------------
__device__ __forceinline__ uint32_t f2tf32(float f) {
    uint32_t r;
    asm("cvt.rna.tf32.f32 %0, %1;" : "=r"(r) : "f"(f));
    return r;
}

__device__ __forceinline__ void mma_tf32(float c[4], const uint32_t a[4], const uint32_t b[2]) {
    asm volatile(
        "mma.sync.aligned.m16n8k8.row.col.f32.tf32.tf32.f32 "
        "{%0,%1,%2,%3}, {%4,%5,%6,%7}, {%8,%9}, {%0,%1,%2,%3};"
        : "+f"(c[0]), "+f"(c[1]), "+f"(c[2]), "+f"(c[3])
        : "r"(a[0]), "r"(a[1]), "r"(a[2]), "r"(a[3]),
          "r"(b[0]), "r"(b[1]));
}

// ---------------------------------------------------------------------------
// tf32 tensor-core GEMM: C[M,N] = A[M,K] @ B[K,N] + bias[N]  (unchanged R1)
// ---------------------------------------------------------------------------
__global__ __launch_bounds__(256, 2)
void gemm_tf32_kernel(const float* __restrict__ A,
                      const float* __restrict__ B,
                      const float* __restrict__ bias,
                      float* __restrict__ C,
                      int M, int N, int K) {
    __shared__ uint32_t As[16][132];
    __shared__ uint32_t Bs[16][132];

    const int tid  = threadIdx.x;
    const int w    = tid >> 5;
    const int lane = tid & 31;
    const int gid  = lane >> 2;
    const int tig  = lane & 3;
    const int wm   = w >> 2;
    const int wn   = w & 3;

    const int rowBase = blockIdx.y * 128;
    const int colBase = blockIdx.x * 128;

    float acc[4][4][4];
    #pragma unroll
    for (int mt = 0; mt < 4; mt++)
        #pragma unroll
        for (int nt = 0; nt < 4; nt++)
            #pragma unroll
            for (int r = 0; r < 4; r++) acc[mt][nt][r] = 0.0f;

    for (int k0 = 0; k0 < K; k0 += 16) {
        #pragma unroll
        for (int i = tid; i < 512; i += 256) {
            int m  = i >> 2;
            int kq = (i & 3) << 2;
            float4 v = *reinterpret_cast<const float4*>(
                &A[(size_t)(rowBase + m) * K + k0 + kq]);
            As[kq + 0][m] = f2tf32(v.x);
            As[kq + 1][m] = f2tf32(v.y);
            As[kq + 2][m] = f2tf32(v.z);
            As[kq + 3][m] = f2tf32(v.w);
        }
        #pragma unroll
        for (int i = tid; i < 512; i += 256) {
            int k  = i >> 5;
            int nq = (i & 31) << 2;
            float4 v = *reinterpret_cast<const float4*>(
                &B[(size_t)(k0 + k) * N + colBase + nq]);
            Bs[k][nq + 0] = f2tf32(v.x);
            Bs[k][nq + 1] = f2tf32(v.y);
            Bs[k][nq + 2] = f2tf32(v.z);
            Bs[k][nq + 3] = f2tf32(v.w);
        }
        __syncthreads();

        #pragma unroll
        for (int kk = 0; kk < 2; kk++) {
            const int kb = kk * 8;
            uint32_t afr[4][4], bfr[4][2];
            #pragma unroll
            for (int mt = 0; mt < 4; mt++) {
                int m = wm * 64 + mt * 16;
                afr[mt][0] = As[kb + tig    ][m + gid    ];
                afr[mt][1] = As[kb + tig    ][m + gid + 8];
                afr[mt][2] = As[kb + tig + 4][m + gid    ];
                afr[mt][3] = As[kb + tig + 4][m + gid + 8];
            }
            #pragma unroll
            for (int nt = 0; nt < 4; nt++) {
                int n = wn * 32 + nt * 8;
                bfr[nt][0] = Bs[kb + tig    ][n + gid];
                bfr[nt][1] = Bs[kb + tig + 4][n + gid];
            }
            #pragma unroll
            for (int mt = 0; mt < 4; mt++)
                #pragma unroll
                for (int nt = 0; nt < 4; nt++)
                    mma_tf32(acc[mt][nt], afr[mt], bfr[nt]);
        }
        __syncthreads();
    }

    #pragma unroll
    for (int mt = 0; mt < 4; mt++) {
        int r0 = rowBase + wm * 64 + mt * 16 + gid;
        #pragma unroll
        for (int nt = 0; nt < 4; nt++) {
            int c0 = colBase + wn * 32 + nt * 8 + 2 * tig;
            float bi0 = bias[c0], bi1 = bias[c0 + 1];
            float2 v0 = make_float2(acc[mt][nt][0] + bi0, acc[mt][nt][1] + bi1);
            float2 v1 = make_float2(acc[mt][nt][2] + bi0, acc[mt][nt][3] + bi1);
            *reinterpret_cast<float2*>(&C[(size_t)r0       * N + c0]) = v0;
            *reinterpret_cast<float2*>(&C[(size_t)(r0 + 8) * N + c0]) = v1;
        }
    }
}

// ---------------------------------------------------------------------------
// tf32 tensor-core flash attention (causal).
// 128 threads = 4 warps. CTA = (b, h, 64 Q rows); warp owns 16 Q rows.
// KV tiles of 64. Q fragments hoisted to registers. P aliases Ks smem.
// smem stride 68 (mod 32 == 4) -> conflict-free K-pattern fragment LDS.
// ---------------------------------------------------------------------------
__global__ __launch_bounds__(128)
void attn_tf32_kernel() {
    const int qt = blockIdx.x;   // 0..31
    const int h  = blockIdx.y;   // 0..15
    const int b  = blockIdx.z;   // 0..1

    __shared__ uint32_t Ks[64][68];   // K tile (tf32); aliased as P after QK^T
    __shared__ uint32_t Vs[64][68];   // V tile (tf32)

    const int tid  = threadIdx.x;
    const int warp = tid >> 5;
    const int lane = tid & 31;
    const int gid  = lane >> 2;   // 0..7
    const int tig  = lane & 3;    // 0..3
    const int wrow = warp * 16;
    const int qrow0 = qt * 64;
    const float scale = 0.125f;   // 1/sqrt(64)

    // Hoist Q fragments (reused across all KV tiles)
    uint32_t qf[8][4];
    {
        const float* Qb = g_qkv + (size_t)(b * LSEQ + qrow0 + wrow) * 3072 + h * 64;
        #pragma unroll
        for (int kc = 0; kc < 8; kc++) {
            qf[kc][0] = f2tf32(Qb[(size_t)gid       * 3072 + kc * 8 + tig    ]);
            qf[kc][1] = f2tf32(Qb[(size_t)(gid + 8) * 3072 + kc * 8 + tig    ]);
            qf[kc][2] = f2tf32(Qb[(size_t)gid       * 3072 + kc * 8 + tig + 4]);
            qf[kc][3] = f2tf32(Qb[(size_t)(gid + 8) * 3072 + kc * 8 + tig + 4]);
        }
    }

    float o[8][4];
    #pragma unroll
    for (int nt = 0; nt < 8; nt++)
        #pragma unroll
        for (int j = 0; j < 4; j++) o[nt][j] = 0.0f;
    float m0 = -1e30f, m8 = -1e30f, l0 = 0.0f, l8 = 0.0f;

    for (int kt = 0; kt <= qt; kt++) {
        const int kv0 = kt * 64;

        // Load K,V tiles [64,64] -> tf32 smem
        #pragma unroll
        for (int i = tid; i < 1024; i += 128) {
            int r  = i >> 4;
            int dq = (i & 15) << 2;
            const float* src = g_qkv + (size_t)(b * LSEQ + kv0 + r) * 3072 + h * 64 + dq;
            float4 kv4 = *reinterpret_cast<const float4*>(src + 1024);
            float4 vv4 = *reinterpret_cast<const float4*>(src + 2048);
            Ks[r][dq + 0] = f2tf32(kv4.x); Ks[r][dq + 1] = f2tf32(kv4.y);
            Ks[r][dq + 2] = f2tf32(kv4.z); Ks[r][dq + 3] = f2tf32(kv4.w);
            Vs[r][dq + 0] = f2tf32(vv4.x); Vs[r][dq + 1] = f2tf32(vv4.y);
            Vs[r][dq + 2] = f2tf32(vv4.z); Vs[r][dq + 3] = f2tf32(vv4.w);
        }
        __syncthreads();

        // S = Q @ K^T  (per-warp 16x64, fp32 accum)
        float s[8][4];
        #pragma unroll
        for (int nt = 0; nt < 8; nt++)
            #pragma unroll
            for (int j = 0; j < 4; j++) s[nt][j] = 0.0f;

        #pragma unroll
        for (int kc = 0; kc < 8; kc++) {
            #pragma unroll
            for (int nt = 0; nt < 8; nt++) {
                uint32_t bfr[2];
                bfr[0] = Ks[nt * 8 + gid][kc * 8 + tig    ];
                bfr[1] = Ks[nt * 8 + gid][kc * 8 + tig + 4];
                mma_tf32(s[nt], qf[kc], bfr);
            }
        }
        __syncthreads();   // everyone done reading Ks before P overwrites it

        // scale + causal mask (only diagonal tile crosses)
        #pragma unroll
        for (int nt = 0; nt < 8; nt++)
            #pragma unroll
            for (int j = 0; j < 4; j++) s[nt][j] *= scale;

        if (kt == qt) {
            const int r0 = wrow + gid, r8 = r0 + 8;
            #pragma unroll
            for (int nt = 0; nt < 8; nt++) {
                int c = nt * 8 + 2 * tig;
                if (c     > r0) s[nt][0] = -1e30f;
                if (c + 1 > r0) s[nt][1] = -1e30f;
                if (c     > r8) s[nt][2] = -1e30f;
                if (c + 1 > r8) s[nt][3] = -1e30f;
            }
        }

        // Online softmax (rows gid and gid+8 of the warp slab)
        float mt0 = -1e30f, mt8 = -1e30f;
        #pragma unroll
        for (int nt = 0; nt < 8; nt++) {
            mt0 = fmaxf(mt0, fmaxf(s[nt][0], s[nt][1]));
            mt8 = fmaxf(mt8, fmaxf(s[nt][2], s[nt][3]));
        }
        #pragma unroll
        for (int off = 1; off < 4; off <<= 1) {
            mt0 = fmaxf(mt0, __shfl_xor_sync(0xffffffffu, mt0, off));
            mt8 = fmaxf(mt8, __shfl_xor_sync(0xffffffffu, mt8, off));
        }
        const float mn0 = fmaxf(m0, mt0), mn8 = fmaxf(m8, mt8);
        const float a0 = __expf(m0 - mn0), a8 = __expf(m8 - mn8);

        float rs0 = 0.0f, rs8 = 0.0f;
        #pragma unroll
        for (int nt = 0; nt < 8; nt++) {
            float p00 = __expf(s[nt][0] - mn0);
            float p01 = __expf(s[nt][1] - mn0);
            float p80 = __expf(s[nt][2] - mn8);
            float p81 = __expf(s[nt][3] - mn8);
            rs0 += p00 + p01;
            rs8 += p80 + p81;
            // P into Ks alias (per-warp slab rows wrow..wrow+15)
            int c = nt * 8 + 2 * tig;
            Ks[wrow + gid    ][c    ] = f2tf32(p00);
            Ks[wrow + gid    ][c + 1] = f2tf32(p01);
            Ks[wrow + gid + 8][c    ] = f2tf32(p80);
            Ks[wrow + gid + 8][c + 1] = f2tf32(p81);
            // rescale O
            o[nt][0] *= a0; o[nt][1] *= a0;
            o[nt][2] *= a8; o[nt][3] *= a8;
        }
        #pragma unroll
        for (int off = 1; off < 4; off <<= 1) {
            rs0 += __shfl_xor_sync(0xffffffffu, rs0, off);
            rs8 += __shfl_xor_sync(0xffffffffu, rs8, off);
        }
        l0 = l0 * a0 + rs0;
        l8 = l8 * a8 + rs8;
        m0 = mn0; m8 = mn8;
        __syncwarp();

        // O += P @ V  (per-warp slab; Ps region is warp-private)
        #pragma unroll
        for (int kc = 0; kc < 8; kc++) {
            uint32_t af[4];
            af[0] = Ks[wrow + gid    ][kc * 8 + tig    ];
            af[1] = Ks[wrow + gid + 8][kc * 8 + tig    ];
            af[2] = Ks[wrow + gid    ][kc * 8 + tig + 4];
            af[3] = Ks[wrow + gid + 8][kc * 8 + tig + 4];
            #pragma unroll
            for (int nt = 0; nt < 8; nt++) {
                uint32_t bfr[2];
                bfr[0] = Vs[kc * 8 + tig    ][nt * 8 + gid];
                bfr[1] = Vs[kc * 8 + tig + 4][nt * 8 + gid];
                mma_tf32(o[nt], af, bfr);
            }
        }
        __syncthreads();   // before next tile's K/V load overwrites smem
    }

    // Epilogue: normalize, store to [B, L, H, hd]
    const float inv0 = 1.0f / l0, inv8 = 1.0f / l8;
    float* dst = g_attn + (size_t)(b * LSEQ + qrow0 + wrow) * D_MODEL + h * 64;
    #pragma unroll
    for (int nt = 0; nt < 8; nt++) {
        int c = nt * 8 + 2 * tig;
        float2 v0 = make_float2(o[nt][0] * inv0, o[nt][1] * inv0);
        float2 v1 = make_float2(o[nt][2] * inv8, o[nt][3] * inv8);
        *reinterpret_cast<float2*>(dst + (size_t)gid       * D_MODEL + c) = v0;
        *reinterpret_cast<float2*>(dst + (size_t)(gid + 8) * D_MODEL + c) = v1;
    }
}

// ---------------------------------------------------------------------------
extern "C" void kernel_launch(void* const* d_in, const int* in_sizes, int n_in,
                              void* d_out, int out_size) {
    const float* x     = (const float*)d_in[0];
    const float* W_qkv = (const float*)d_in[1];
    const float* b_qkv = (const float*)d_in[2];
    const float* W_out = (const float*)d_in[3];
    const float* b_out = (const float*)d_in[4];
    float* out = (float*)d_out;

    float* qkv;  cudaGetSymbolAddress((void**)&qkv,  g_qkv);
    float* attn; cudaGetSymbolAddress((void**)&attn, g_attn);

    // 1) QKV projection (tf32 TC)
    dim3 g1(3 * D_MODEL / 128, NTOK / 128);
    gemm_tf32_kernel<<<g1, 256>>>(x, W_qkv, b_qkv, qkv, NTOK, 3 * D_MODEL, D_MODEL);

    // 2) Causal flash attention (tf32 TC)
    dim3 g2(LSEQ / 64, NHEAD, NB);
    attn_tf32_kernel<<<g2, 128>>>();

    // 3) Output projection (tf32 TC)
    dim3 g3(D_MODEL / 128, NTOK / 128);
    gemm_tf32_kernel<<<g3, 256>>>(attn, W_out, b_out, out, NTOK, D_MODEL, D_MODEL);
}

// round 5
// speedup vs baseline: 3.9039x; 1.2407x over previous
#include <cuda_runtime.h>
#include <cstdint>

#define D_MODEL 1024
#define LSEQ    2048
#define NB      2
#define NHEAD   16
#define HD      64
#define NTOK    (NB * LSEQ)   // 4096

// Scratch (device globals — alloc-free per harness rules)
__device__ float g_qkv[(size_t)NTOK * 3 * D_MODEL];   // [4096, 3072]
__device__ float g_attn[(size_t)NTOK * D_MODEL];      // [4096, 1024] = [B,L,H,hd]

// ---------------------------------------------------------------------------
// tf32 helpers
// ---------------------------------------------------------------------------
__device__ __forceinline__ uint32_t f2tf32(float f) {
    uint32_t r;
    asm("cvt.rna.tf32.f32 %0, %1;" : "=r"(r) : "f"(f));
    return r;
}

__device__ __forceinline__ void mma_tf32(float c[4], const uint32_t a[4], const uint32_t b[2]) {
    asm volatile(
        "mma.sync.aligned.m16n8k8.row.col.f32.tf32.tf32.f32 "
        "{%0,%1,%2,%3}, {%4,%5,%6,%7}, {%8,%9}, {%0,%1,%2,%3};"
        : "+f"(c[0]), "+f"(c[1]), "+f"(c[2]), "+f"(c[3])
        : "r"(a[0]), "r"(a[1]), "r"(a[2]), "r"(a[3]),
          "r"(b[0]), "r"(b[1]));
}

__device__ __forceinline__ void cp_async16(void* smem_dst, const void* gmem_src) {
    uint32_t dst;
    asm("{ .reg .u64 t; cvta.to.shared.u64 t, %1; cvt.u32.u64 %0, t; }"
        : "=r"(dst) : "l"(smem_dst));
    asm volatile("cp.async.cg.shared.global [%0], [%1], 16;" :: "r"(dst), "l"(gmem_src));
}
__device__ __forceinline__ void cp_async_commit() {
    asm volatile("cp.async.commit_group;");
}
template <int N>
__device__ __forceinline__ void cp_async_wait() {
    asm volatile("cp.async.wait_group %0;" :: "n"(N));
}

// ---------------------------------------------------------------------------
// tf32 tensor-core GEMM with 3-stage cp.async pipeline.
// Invariant: k-block j lives in buffer j % STAGES.  (R3 bug: stored into
// iter % STAGES — fixed.)
// ---------------------------------------------------------------------------
#define STAGES 3

__global__ __launch_bounds__(256, 2)
void gemm_tf32_kernel(const float* __restrict__ A,
                      const float* __restrict__ B,
                      const float* __restrict__ bias,
                      float* __restrict__ C,
                      int M, int N, int K) {
    __shared__ float As[STAGES][128][20];
    __shared__ float Bs[STAGES][16][136];

    const int tid  = threadIdx.x;
    const int w    = tid >> 5;
    const int lane = tid & 31;
    const int gid  = lane >> 2;   // 0..7
    const int tig  = lane & 3;    // 0..3
    const int wm   = w >> 2;      // 0..1
    const int wn   = w & 3;       // 0..3

    const int rowBase = blockIdx.y * 128;
    const int colBase = blockIdx.x * 128;

    // A tile: 128 rows x 4 float4-chunks = 512; thread handles chunks tid, tid+256
    const int a_row0 = tid >> 2,         a_kq0 = (tid & 3) << 2;
    const int a_row1 = (tid + 256) >> 2, a_kq1 = ((tid + 256) & 3) << 2;
    // B tile: 16 rows x 32 chunks = 512; thread handles chunks tid, tid+256
    const int b_row0 = tid >> 5,         b_nq0 = (tid & 31) << 2;
    const int b_row1 = (tid + 256) >> 5, b_nq1 = ((tid + 256) & 31) << 2;

    float acc[4][4][4];
    #pragma unroll
    for (int mt = 0; mt < 4; mt++)
        #pragma unroll
        for (int nt = 0; nt < 4; nt++)
            #pragma unroll
            for (int r = 0; r < 4; r++) acc[mt][nt][r] = 0.0f;

    const int KITERS = K >> 4;

    // Prefetch k-blocks 0..STAGES-2 into their home buffers
    #pragma unroll
    for (int s = 0; s < STAGES - 1; s++) {
        const int k0 = s << 4;
        cp_async16(&As[s][a_row0][a_kq0], &A[(size_t)(rowBase + a_row0) * K + k0 + a_kq0]);
        cp_async16(&As[s][a_row1][a_kq1], &A[(size_t)(rowBase + a_row1) * K + k0 + a_kq1]);
        cp_async16(&Bs[s][b_row0][b_nq0], &B[(size_t)(k0 + b_row0) * N + colBase + b_nq0]);
        cp_async16(&Bs[s][b_row1][b_nq1], &B[(size_t)(k0 + b_row1) * N + colBase + b_nq1]);
        cp_async_commit();
    }

    for (int iter = 0; iter < KITERS; iter++) {
        const int buf = iter % STAGES;
        cp_async_wait<STAGES - 2>();
        __syncthreads();

        #pragma unroll
        for (int kk = 0; kk < 2; kk++) {
            const int kb = kk * 8;
            uint32_t afr[4][4], bfr[4][2];
            #pragma unroll
            for (int mt = 0; mt < 4; mt++) {
                int m = wm * 64 + mt * 16;
                afr[mt][0] = f2tf32(As[buf][m + gid    ][kb + tig    ]);
                afr[mt][1] = f2tf32(As[buf][m + gid + 8][kb + tig    ]);
                afr[mt][2] = f2tf32(As[buf][m + gid    ][kb + tig + 4]);
                afr[mt][3] = f2tf32(As[buf][m + gid + 8][kb + tig + 4]);
            }
            #pragma unroll
            for (int nt = 0; nt < 4; nt++) {
                int n = wn * 32 + nt * 8;
                bfr[nt][0] = f2tf32(Bs[buf][kb + tig    ][n + gid]);
                bfr[nt][1] = f2tf32(Bs[buf][kb + tig + 4][n + gid]);
            }
            #pragma unroll
            for (int mt = 0; mt < 4; mt++)
                #pragma unroll
                for (int nt = 0; nt < 4; nt++)
                    mma_tf32(acc[mt][nt], afr[mt], bfr[nt]);
        }
        __syncthreads();   // all warps done with oldest buffers before refill

        const int kload = iter + STAGES - 1;
        if (kload < KITERS) {
            const int sbuf = kload % STAGES;     // FIX: home buffer of k-block kload
            const int k0 = kload << 4;
            cp_async16(&As[sbuf][a_row0][a_kq0], &A[(size_t)(rowBase + a_row0) * K + k0 + a_kq0]);
            cp_async16(&As[sbuf][a_row1][a_kq1], &A[(size_t)(rowBase + a_row1) * K + k0 + a_kq1]);
            cp_async16(&Bs[sbuf][b_row0][b_nq0], &B[(size_t)(k0 + b_row0) * N + colBase + b_nq0]);
            cp_async16(&Bs[sbuf][b_row1][b_nq1], &B[(size_t)(k0 + b_row1) * N + colBase + b_nq1]);
        }
        cp_async_commit();
    }

    // Epilogue: add bias, store as float2 pairs
    #pragma unroll
    for (int mt = 0; mt < 4; mt++) {
        int r0 = rowBase + wm * 64 + mt * 16 + gid;
        #pragma unroll
        for (int nt = 0; nt < 4; nt++) {
            int c0 = colBase + wn * 32 + nt * 8 + 2 * tig;
            float bi0 = bias[c0], bi1 = bias[c0 + 1];
            float2 v0 = make_float2(acc[mt][nt][0] + bi0, acc[mt][nt][1] + bi1);
            float2 v1 = make_float2(acc[mt][nt][2] + bi0, acc[mt][nt][3] + bi1);
            *reinterpret_cast<float2*>(&C[(size_t)r0       * N + c0]) = v0;
            *reinterpret_cast<float2*>(&C[(size_t)(r0 + 8) * N + c0]) = v1;
        }
    }
}

// ---------------------------------------------------------------------------
// tf32 tensor-core flash attention (causal). Unchanged from R2 (passing).
// ---------------------------------------------------------------------------
__global__ __launch_bounds__(128)
void attn_tf32_kernel() {
    const int qt = blockIdx.x;
    const int h  = blockIdx.y;
    const int b  = blockIdx.z;

    __shared__ uint32_t Ks[64][68];
    __shared__ uint32_t Vs[64][68];

    const int tid  = threadIdx.x;
    const int warp = tid >> 5;
    const int lane = tid & 31;
    const int gid  = lane >> 2;
    const int tig  = lane & 3;
    const int wrow = warp * 16;
    const int qrow0 = qt * 64;
    const float scale = 0.125f;

    uint32_t qf[8][4];
    {
        const float* Qb = g_qkv + (size_t)(b * LSEQ + qrow0 + wrow) * 3072 + h * 64;
        #pragma unroll
        for (int kc = 0; kc < 8; kc++) {
            qf[kc][0] = f2tf32(Qb[(size_t)gid       * 3072 + kc * 8 + tig    ]);
            qf[kc][1] = f2tf32(Qb[(size_t)(gid + 8) * 3072 + kc * 8 + tig    ]);
            qf[kc][2] = f2tf32(Qb[(size_t)gid       * 3072 + kc * 8 + tig + 4]);
            qf[kc][3] = f2tf32(Qb[(size_t)(gid + 8) * 3072 + kc * 8 + tig + 4]);
        }
    }

    float o[8][4];
    #pragma unroll
    for (int nt = 0; nt < 8; nt++)
        #pragma unroll
        for (int j = 0; j < 4; j++) o[nt][j] = 0.0f;
    float m0 = -1e30f, m8 = -1e30f, l0 = 0.0f, l8 = 0.0f;

    for (int kt = 0; kt <= qt; kt++) {
        const int kv0 = kt * 64;

        #pragma unroll
        for (int i = tid; i < 1024; i += 128) {
            int r  = i >> 4;
            int dq = (i & 15) << 2;
            const float* src = g_qkv + (size_t)(b * LSEQ + kv0 + r) * 3072 + h * 64 + dq;
            float4 kv4 = *reinterpret_cast<const float4*>(src + 1024);
            float4 vv4 = *reinterpret_cast<const float4*>(src + 2048);
            Ks[r][dq + 0] = f2tf32(kv4.x); Ks[r][dq + 1] = f2tf32(kv4.y);
            Ks[r][dq + 2] = f2tf32(kv4.z); Ks[r][dq + 3] = f2tf32(kv4.w);
            Vs[r][dq + 0] = f2tf32(vv4.x); Vs[r][dq + 1] = f2tf32(vv4.y);
            Vs[r][dq + 2] = f2tf32(vv4.z); Vs[r][dq + 3] = f2tf32(vv4.w);
        }
        __syncthreads();

        float s[8][4];
        #pragma unroll
        for (int nt = 0; nt < 8; nt++)
            #pragma unroll
            for (int j = 0; j < 4; j++) s[nt][j] = 0.0f;

        #pragma unroll
        for (int kc = 0; kc < 8; kc++) {
            #pragma unroll
            for (int nt = 0; nt < 8; nt++) {
                uint32_t bfr[2];
                bfr[0] = Ks[nt * 8 + gid][kc * 8 + tig    ];
                bfr[1] = Ks[nt * 8 + gid][kc * 8 + tig + 4];
                mma_tf32(s[nt], qf[kc], bfr);
            }
        }
        __syncthreads();

        #pragma unroll
        for (int nt = 0; nt < 8; nt++)
            #pragma unroll
            for (int j = 0; j < 4; j++) s[nt][j] *= scale;

        if (kt == qt) {
            const int r0 = wrow + gid, r8 = r0 + 8;
            #pragma unroll
            for (int nt = 0; nt < 8; nt++) {
                int c = nt * 8 + 2 * tig;
                if (c     > r0) s[nt][0] = -1e30f;
                if (c + 1 > r0) s[nt][1] = -1e30f;
                if (c     > r8) s[nt][2] = -1e30f;
                if (c + 1 > r8) s[nt][3] = -1e30f;
            }
        }

        float mt0 = -1e30f, mt8 = -1e30f;
        #pragma unroll
        for (int nt = 0; nt < 8; nt++) {
            mt0 = fmaxf(mt0, fmaxf(s[nt][0], s[nt][1]));
            mt8 = fmaxf(mt8, fmaxf(s[nt][2], s[nt][3]));
        }
        #pragma unroll
        for (int off = 1; off < 4; off <<= 1) {
            mt0 = fmaxf(mt0, __shfl_xor_sync(0xffffffffu, mt0, off));
            mt8 = fmaxf(mt8, __shfl_xor_sync(0xffffffffu, mt8, off));
        }
        const float mn0 = fmaxf(m0, mt0), mn8 = fmaxf(m8, mt8);
        const float a0 = __expf(m0 - mn0), a8 = __expf(m8 - mn8);

        float rs0 = 0.0f, rs8 = 0.0f;
        #pragma unroll
        for (int nt = 0; nt < 8; nt++) {
            float p00 = __expf(s[nt][0] - mn0);
            float p01 = __expf(s[nt][1] - mn0);
            float p80 = __expf(s[nt][2] - mn8);
            float p81 = __expf(s[nt][3] - mn8);
            rs0 += p00 + p01;
            rs8 += p80 + p81;
            int c = nt * 8 + 2 * tig;
            Ks[wrow + gid    ][c    ] = f2tf32(p00);
            Ks[wrow + gid    ][c + 1] = f2tf32(p01);
            Ks[wrow + gid + 8][c    ] = f2tf32(p80);
            Ks[wrow + gid + 8][c + 1] = f2tf32(p81);
            o[nt][0] *= a0; o[nt][1] *= a0;
            o[nt][2] *= a8; o[nt][3] *= a8;
        }
        #pragma unroll
        for (int off = 1; off < 4; off <<= 1) {
            rs0 += __shfl_xor_sync(0xffffffffu, rs0, off);
            rs8 += __shfl_xor_sync(0xffffffffu, rs8, off);
        }
        l0 = l0 * a0 + rs0;
        l8 = l8 * a8 + rs8;
        m0 = mn0; m8 = mn8;
        __syncwarp();

        #pragma unroll
        for (int kc = 0; kc < 8; kc++) {
            uint32_t af[4];
            af[0] = Ks[wrow + gid    ][kc * 8 + tig    ];
            af[1] = Ks[wrow + gid + 8][kc * 8 + tig    ];
            af[2] = Ks[wrow + gid    ][kc * 8 + tig + 4];
            af[3] = Ks[wrow + gid + 8][kc * 8 + tig + 4];
            #pragma unroll
            for (int nt = 0; nt < 8; nt++) {
                uint32_t bfr[2];
                bfr[0] = Vs[kc * 8 + tig    ][nt * 8 + gid];
                bfr[1] = Vs[kc * 8 + tig + 4][nt * 8 + gid];
                mma_tf32(o[nt], af, bfr);
            }
        }
        __syncthreads();
    }

    const float inv0 = 1.0f / l0, inv8 = 1.0f / l8;
    float* dst = g_attn + (size_t)(b * LSEQ + qrow0 + wrow) * D_MODEL + h * 64;
    #pragma unroll
    for (int nt = 0; nt < 8; nt++) {
        int c = nt * 8 + 2 * tig;
        float2 v0 = make_float2(o[nt][0] * inv0, o[nt][1] * inv0);
        float2 v1 = make_float2(o[nt][2] * inv8, o[nt][3] * inv8);
        *reinterpret_cast<float2*>(dst + (size_t)gid       * D_MODEL + c) = v0;
        *reinterpret_cast<float2*>(dst + (size_t)(gid + 8) * D_MODEL + c) = v1;
    }
}

// ---------------------------------------------------------------------------
extern "C" void kernel_launch(void* const* d_in, const int* in_sizes, int n_in,
                              void* d_out, int out_size) {
    const float* x     = (const float*)d_in[0];
    const float* W_qkv = (const float*)d_in[1];
    const float* b_qkv = (const float*)d_in[2];
    const float* W_out = (const float*)d_in[3];
    const float* b_out = (const float*)d_in[4];
    float* out = (float*)d_out;

    float* qkv;  cudaGetSymbolAddress((void**)&qkv,  g_qkv);
    float* attn; cudaGetSymbolAddress((void**)&attn, g_attn);

    dim3 g1(3 * D_MODEL / 128, NTOK / 128);
    gemm_tf32_kernel<<<g1, 256>>>(x, W_qkv, b_qkv, qkv, NTOK, 3 * D_MODEL, D_MODEL);

    dim3 g2(LSEQ / 64, NHEAD, NB);
    attn_tf32_kernel<<<g2, 128>>>();

    dim3 g3(D_MODEL / 128, NTOK / 128);
    gemm_tf32_kernel<<<g3, 256>>>(attn, W_out, b_out, out, NTOK, D_MODEL, D_MODEL);
}